// round 2
// baseline (speedup 1.0000x reference)
#include <cuda_runtime.h>
#include <math.h>

#define NB 128u   // CTAs in the persistent recurrent kernel

// ---------------- device scratch (no allocation allowed) ----------------
__device__ float g_pre[(size_t)16384 * 3072];   // [t*32+b][3072]: fwG(1024) fwC(512) bwG(1024) bwC(512)
__device__ float g_xt [(size_t)512 * 32 * 256]; // x transposed: [t][b][256]
__device__ float g_outf[(size_t)512 * 32 * 512];// fw hidden [t][b][512]
__device__ float g_outb[(size_t)512 * 32 * 512];// bw hidden [t][b][512]
__device__ float g_h  [2 * 32 * 512];           // current h [d][b][512]
__device__ float g_ru [2 * 32 * 1024];          // sigmoided gates [d][b][1024] (r: 0..511, u: 512..1023)
__device__ float g_pool[32 * 512];              // max-pool result
__device__ unsigned g_cnt;
__device__ volatile unsigned g_gen;

// ---------------- init ----------------
__global__ void k_init() {
    int i = blockIdx.x * blockDim.x + threadIdx.x;
    if (i < 2 * 32 * 512) g_h[i] = 0.f;
    if (i < 32 * 512)     g_pool[i] = 0.f;
    if (i == 0) { g_cnt = 0u; *(unsigned*)&g_gen = 0u; }
}

// ---------------- x -> [t][b][c] copy ----------------
__global__ void k_xcopy(const float* __restrict__ x) {
    int idx = blockIdx.x * blockDim.x + threadIdx.x;  // float4 id
    if (idx < 32 * 512 * 64) {
        int row = idx >> 6, c4 = idx & 63;            // row = b*512 + t
        int b = row >> 9, t = row & 511;
        ((float4*)g_xt)[(size_t)(t * 32 + b) * 64 + c4] = ((const float4*)x)[idx];
    }
}

// ---------------- GEMM1: x-part projections (M=16384,K=256,N=3072) ----------------
__global__ __launch_bounds__(256) void k_gemm_pre(
    const float* __restrict__ x,
    const float* __restrict__ fwWg, const float* __restrict__ fwbg,
    const float* __restrict__ fwWc, const float* __restrict__ fwbc,
    const float* __restrict__ bwWg, const float* __restrict__ bwbg,
    const float* __restrict__ bwWc, const float* __restrict__ bwbc)
{
    __shared__ float As[16 * 132];
    __shared__ float Bs[16 * 68];
    const int n0 = blockIdx.x * 64;
    const int m0 = blockIdx.y * 128;
    const float* W; const float* bias; int ld, nrel;
    if (n0 < 1024)      { W = fwWg; bias = fwbg; ld = 1024; nrel = n0; }
    else if (n0 < 1536) { W = fwWc; bias = fwbc; ld = 512;  nrel = n0 - 1024; }
    else if (n0 < 2560) { W = bwWg; bias = bwbg; ld = 1024; nrel = n0 - 1536; }
    else                { W = bwWc; bias = bwbc; ld = 512;  nrel = n0 - 2560; }
    const int tid = threadIdx.x;
    const int tx = tid & 15, ty = tid >> 4;
    float acc[8][4];
#pragma unroll
    for (int i = 0; i < 8; i++)
#pragma unroll
        for (int j = 0; j < 4; j++) acc[i][j] = 0.f;

    for (int k0 = 0; k0 < 256; k0 += 16) {
#pragma unroll
        for (int i = 0; i < 2; ++i) {
            int f = tid + i * 256;
            int r = f >> 2, c4 = (f & 3) * 4;
            float4 v = *(const float4*)&x[(size_t)(m0 + r) * 256 + k0 + c4];
            As[(c4 + 0) * 132 + r] = v.x;
            As[(c4 + 1) * 132 + r] = v.y;
            As[(c4 + 2) * 132 + r] = v.z;
            As[(c4 + 3) * 132 + r] = v.w;
        }
        {
            int kk = tid >> 4, nn = (tid & 15) * 4;
            *(float4*)&Bs[kk * 68 + nn] = *(const float4*)&W[(size_t)(k0 + kk) * ld + nrel + nn];
        }
        __syncthreads();
#pragma unroll
        for (int kk = 0; kk < 16; ++kk) {
            float a[8], w[4];
            *(float4*)&a[0] = *(float4*)&As[kk * 132 + ty * 8];
            *(float4*)&a[4] = *(float4*)&As[kk * 132 + ty * 8 + 4];
            *(float4*)&w[0] = *(float4*)&Bs[kk * 68 + tx * 4];
#pragma unroll
            for (int i = 0; i < 8; i++)
#pragma unroll
                for (int j = 0; j < 4; j++) acc[i][j] += a[i] * w[j];
        }
        __syncthreads();
    }
    float4 bv = *(const float4*)&bias[nrel + tx * 4];
#pragma unroll
    for (int i = 0; i < 8; i++) {
        int m = m0 + ty * 8 + i;
        int trow = (m & 511) * 32 + (m >> 9);   // -> [t][b]
        float4 o = make_float4(acc[i][0] + bv.x, acc[i][1] + bv.y,
                               acc[i][2] + bv.z, acc[i][3] + bv.w);
        *(float4*)&g_pre[(size_t)trow * 3072 + n0 + tx * 4] = o;
    }
}

// ---------------- grid barrier (monotonic count, safe across replays) ----------------
__device__ __forceinline__ void gsync(unsigned target) {
    __syncthreads();
    if (threadIdx.x == 0) {
        __threadfence();
        unsigned arr = atomicAdd(&g_cnt, 1u) + 1u;
        if (arr == target * NB) {
            atomicExch((unsigned*)&g_gen, target);
        } else {
            while (g_gen < target) __nanosleep(40);
        }
        __threadfence();
    }
    __syncthreads();
}

// ---------------- persistent bidirectional GRU ----------------
// 128 CTAs: dir = cta/64; each CTA owns 16 gate cols + 8 cand cols (weights pinned in smem).
__global__ __launch_bounds__(256, 1) void k_recur(
    const float* __restrict__ fwWg, const float* __restrict__ fwWc,
    const float* __restrict__ bwWg, const float* __restrict__ bwWc)
{
    extern __shared__ float sm[];
    float* Wg_s = sm;             // 16 x 516
    float* Wc_s = sm + 8256;      // 8 x 516
    float* h_s  = sm + 12384;     // 32*512 floats, float4 XOR-swizzled [b][kc]
    float* red  = sm + 28768;     // 8 x 528 reduction buffer

    const int tid = threadIdx.x;
    const int cta = blockIdx.x;
    const int dir = cta >> 6;
    const int c64 = cta & 63;
    const int jg0 = c64 * 16;
    const int jc0 = c64 * 8;
    const float* Wg = dir ? bwWg : fwWg;
    const float* Wc = dir ? bwWc : fwWc;

    // pin recurrent-weight slices in smem (rows 256..767 are the h-part)
    for (int idx = tid; idx < 16 * 512; idx += 256) {
        int jj = idx & 15, k = idx >> 4;
        Wg_s[jj * 516 + k] = Wg[(size_t)(256 + k) * 1024 + jg0 + jj];
    }
    for (int idx = tid; idx < 8 * 512; idx += 256) {
        int ii = idx & 7, k = idx >> 3;
        Wc_s[ii * 516 + k] = Wc[(size_t)(256 + k) * 512 + jc0 + ii];
    }

    const int warp = tid >> 5;
    const int b = tid & 31;
    const int kc0 = warp * 16;
    float4* h4p = (float4*)h_s;
    const float4* gh4 = (const float4*)g_h;
    const float4* wg4 = (const float4*)Wg_s;
    const float4* wc4 = (const float4*)Wc_s;
    unsigned bar = 0;

    for (int s = 0; s < 512; ++s) {
        const int t = dir ? (511 - s) : s;
        // ---- stage h into swizzled smem ----
        for (int f = tid; f < 4096; f += 256) {
            int bb = f >> 7, kc = f & 127;
            h4p[bb * 128 + (kc ^ (bb & 7))] = gh4[dir * 4096 + f];
        }
        __syncthreads();
        // ---- gate GEMM: warp = k-slice, lanes = batch, 16 cols ----
        {
            float acc[16];
#pragma unroll
            for (int jj = 0; jj < 16; ++jj) acc[jj] = 0.f;
#pragma unroll 4
            for (int kc = kc0; kc < kc0 + 16; ++kc) {
                float4 h4 = h4p[b * 128 + (kc ^ (b & 7))];
#pragma unroll
                for (int jj = 0; jj < 16; ++jj) {
                    float4 w4 = wg4[jj * 129 + kc];
                    acc[jj] += h4.x * w4.x;
                    acc[jj] += h4.y * w4.y;
                    acc[jj] += h4.z * w4.z;
                    acc[jj] += h4.w * w4.w;
                }
            }
#pragma unroll
            for (int jj = 0; jj < 16; ++jj)
                red[warp * 528 + jj * 33 + b] = acc[jj];
        }
        __syncthreads();
        // ---- reduce + sigmoid -> g_ru ----
        for (int o = tid; o < 512; o += 256) {
            int jj = o & 15, bb = o >> 4;
            float v = 0.f;
#pragma unroll
            for (int q = 0; q < 8; ++q) v += red[q * 528 + jj * 33 + bb];
            v += g_pre[(size_t)(t * 32 + bb) * 3072 + (dir ? 1536 : 0) + jg0 + jj];
            g_ru[(dir * 32 + bb) * 1024 + jg0 + jj] = 1.f / (1.f + expf(-v));
        }
        gsync(++bar);
        // ---- phase B: candidate + update ----
        float hold;
        {
            int ii = tid & 7, bb = tid >> 3;
            int i = jc0 + ii;
            hold = h_s[(bb * 128 + ((i >> 2) ^ (bb & 7))) * 4 + (i & 3)];
        }
        __syncthreads();
        // rh = r * h, in place
        for (int f = tid; f < 4096; f += 256) {
            int bb = f >> 7, kc = f & 127;
            float4 r4 = *(const float4*)&g_ru[(dir * 32 + bb) * 1024 + kc * 4];
            int p = bb * 128 + (kc ^ (bb & 7));
            float4 h4 = h4p[p];
            h4.x *= r4.x; h4.y *= r4.y; h4.z *= r4.z; h4.w *= r4.w;
            h4p[p] = h4;
        }
        __syncthreads();
        // cand GEMM: 8 cols
        {
            float acc[8];
#pragma unroll
            for (int ii = 0; ii < 8; ++ii) acc[ii] = 0.f;
#pragma unroll 4
            for (int kc = kc0; kc < kc0 + 16; ++kc) {
                float4 h4 = h4p[b * 128 + (kc ^ (b & 7))];
#pragma unroll
                for (int ii = 0; ii < 8; ++ii) {
                    float4 w4 = wc4[ii * 129 + kc];
                    acc[ii] += h4.x * w4.x;
                    acc[ii] += h4.y * w4.y;
                    acc[ii] += h4.z * w4.z;
                    acc[ii] += h4.w * w4.w;
                }
            }
#pragma unroll
            for (int ii = 0; ii < 8; ++ii)
                red[warp * 264 + ii * 33 + b] = acc[ii];
        }
        __syncthreads();
        {
            int ii = tid & 7, bb = tid >> 3;
            float v = 0.f;
#pragma unroll
            for (int q = 0; q < 8; ++q) v += red[q * 264 + ii * 33 + bb];
            v += g_pre[(size_t)(t * 32 + bb) * 3072 + (dir ? 2560 : 1024) + jc0 + ii];
            float ct = tanhf(v);
            float u = g_ru[(dir * 32 + bb) * 1024 + 512 + jc0 + ii];
            float hn = u * hold + (1.f - u) * ct;
            g_h[(dir * 32 + bb) * 512 + jc0 + ii] = hn;
            float* outp = dir ? g_outb : g_outf;
            outp[(size_t)(t * 32 + bb) * 512 + jc0 + ii] = hn;
        }
        gsync(++bar);
    }
}

// ---------------- FC over shifted-context concat + relu + max-pool ----------------
__global__ __launch_bounds__(256) void k_fc(const float* __restrict__ fcw,
                                            const float* __restrict__ fcb)
{
    __shared__ float As[16 * 132];
    __shared__ float Bs[16 * 68];
    const int n0 = blockIdx.x * 64;
    const int m0 = blockIdx.y * 128;      // m = t*32 + b
    const int tid = threadIdx.x;
    const int tx = tid & 15, ty = tid >> 4;
    float acc[8][4];
#pragma unroll
    for (int i = 0; i < 8; i++)
#pragma unroll
        for (int j = 0; j < 4; j++) acc[i][j] = 0.f;

    for (int k0 = 0; k0 < 1280; k0 += 16) {
#pragma unroll
        for (int i = 0; i < 2; ++i) {
            int f = tid + i * 256;
            int r = f >> 2, c4 = (f & 3) * 4;
            int m = m0 + r;
            int c = k0 + c4;
            float4 v = make_float4(0.f, 0.f, 0.f, 0.f);
            if (k0 < 512) {                       // c_left = out_fw[t-1]
                if (m >= 32) v = *(const float4*)&g_outf[(size_t)(m - 32) * 512 + c];
            } else if (k0 < 768) {                // x[t]
                v = *(const float4*)&g_xt[(size_t)m * 256 + (c - 512)];
            } else {                              // c_right = out_bw[t+1]
                if (m < 16352) v = *(const float4*)&g_outb[(size_t)(m + 32) * 512 + (c - 768)];
            }
            As[(c4 + 0) * 132 + r] = v.x;
            As[(c4 + 1) * 132 + r] = v.y;
            As[(c4 + 2) * 132 + r] = v.z;
            As[(c4 + 3) * 132 + r] = v.w;
        }
        {
            int kk = tid >> 4, nn = (tid & 15) * 4;
            *(float4*)&Bs[kk * 68 + nn] = *(const float4*)&fcw[(size_t)(k0 + kk) * 512 + n0 + nn];
        }
        __syncthreads();
#pragma unroll
        for (int kk = 0; kk < 16; ++kk) {
            float a[8], w[4];
            *(float4*)&a[0] = *(float4*)&As[kk * 132 + ty * 8];
            *(float4*)&a[4] = *(float4*)&As[kk * 132 + ty * 8 + 4];
            *(float4*)&w[0] = *(float4*)&Bs[kk * 68 + tx * 4];
#pragma unroll
            for (int i = 0; i < 8; i++)
#pragma unroll
                for (int j = 0; j < 4; j++) acc[i][j] += a[i] * w[j];
        }
        __syncthreads();
    }
    float4 bv = *(const float4*)&fcb[n0 + tx * 4];
#pragma unroll
    for (int i = 0; i < 8; i++) {
        int m = m0 + ty * 8 + i;
        int bb = m & 31;
        float r0 = fmaxf(acc[i][0] + bv.x, 0.f);
        float r1 = fmaxf(acc[i][1] + bv.y, 0.f);
        float r2 = fmaxf(acc[i][2] + bv.z, 0.f);
        float r3 = fmaxf(acc[i][3] + bv.w, 0.f);
        int base = bb * 512 + n0 + tx * 4;
        atomicMax((int*)&g_pool[base + 0], __float_as_int(r0));
        atomicMax((int*)&g_pool[base + 1], __float_as_int(r1));
        atomicMax((int*)&g_pool[base + 2], __float_as_int(r2));
        atomicMax((int*)&g_pool[base + 3], __float_as_int(r3));
    }
}

// ---------------- MLP head ----------------
__global__ void k_mlp(const float* __restrict__ mw, const float* __restrict__ mb,
                      float* __restrict__ out)
{
    __shared__ float sp[512];
    int bb = blockIdx.x;
    int tid = threadIdx.x;   // 256 -> one output each
    for (int i = tid; i < 512; i += 256) sp[i] = g_pool[bb * 512 + i];
    __syncthreads();
    float acc = mb[tid];
#pragma unroll 8
    for (int h = 0; h < 512; ++h) acc += sp[h] * mw[h * 256 + tid];
    out[bb * 256 + tid] = acc;
}

// ---------------- launch ----------------
extern "C" void kernel_launch(void* const* d_in, const int* in_sizes, int n_in,
                              void* d_out, int out_size)
{
    const float* x    = (const float*)d_in[0];
    const float* fwWg = (const float*)d_in[1];
    const float* fwbg = (const float*)d_in[2];
    const float* fwWc = (const float*)d_in[3];
    const float* fwbc = (const float*)d_in[4];
    const float* bwWg = (const float*)d_in[5];
    const float* bwbg = (const float*)d_in[6];
    const float* bwWc = (const float*)d_in[7];
    const float* bwbc = (const float*)d_in[8];
    const float* fcw  = (const float*)d_in[9];
    const float* fcb  = (const float*)d_in[10];
    const float* mw   = (const float*)d_in[11];
    const float* mb   = (const float*)d_in[12];
    float* out = (float*)d_out;

    cudaFuncSetAttribute(k_recur, cudaFuncAttributeMaxDynamicSharedMemorySize, 131968);

    k_init<<<128, 256>>>();
    k_xcopy<<<4096, 256>>>(x);
    k_gemm_pre<<<dim3(48, 128), 256>>>(x, fwWg, fwbg, fwWc, fwbc, bwWg, bwbg, bwWc, bwbc);
    k_recur<<<128, 256, 131968>>>(fwWg, fwWc, bwWg, bwWc);
    k_fc<<<dim3(8, 128), 256>>>(fcw, fcb);
    k_mlp<<<32, 256>>>(mw, mb, out);
}